// round 10
// baseline (speedup 1.0000x reference)
#include <cuda_runtime.h>
#include <math.h>

#define NB     32
#define NA     33600
#define K_TOP  1000
#define NBINS  2048      // coarse bins: score_bits >> 19
#define NSUB   2048      // refine bins: bits[18:8]
#define NCAND  2048
#define NA4    (NA / 4)  // 8400
#define NDET   (NB * K_TOP)

#define NBLK   288       // 144 SMs x 2 — co-resident on >=148-SM sm_103a
#define NT     512
#define NTHR   (NBLK * NT)

// scratch (static device globals — no allocation)
__device__ float        g_scores[NB * NA];   // 4.3 MB, L2-resident
__device__ int          g_keep[NDET];        // anchor per (batch, rank)
__device__ unsigned int g_bar[2];            // grid barrier counters (zeroed pre-launch)

// Bitwise match of XLA GPU logistic: 1/(1+exp(-x)) with libdevice expf and
// IEEE div.rn (nvcc defaults, no fast-math). DO NOT refactor algebraically —
// output ordering must be bit-exact vs reference (rel_err 5e-9 confirms).
__device__ __forceinline__ float sigref(float x) {
    return 1.0f / (1.0f + expf(-x));
}

// ---------------------------------------------------------------------------
// Kernel 0: reset grid-barrier counters (runs before each replay)
// ---------------------------------------------------------------------------
__global__ void zero_bar() {
    if (threadIdx.x < 2) g_bar[threadIdx.x] = 0u;
}

// Counter grid barrier: all NBLK CTAs are co-resident (launch_bounds enforces
// occupancy 2/SM), so spinning is deadlock-free. Release fence before arrive,
// acquire fence after spin.
__device__ __forceinline__ void grid_bar(int k) {
    __syncthreads();
    if (threadIdx.x == 0) {
        __threadfence();
        atomicAdd(&g_bar[k], 1u);
        while (((volatile unsigned int*)g_bar)[k] < (unsigned int)NBLK) { }
        __threadfence();
    }
    __syncthreads();
}

// ---------------------------------------------------------------------------
// find_thresh for 512 threads: largest bin T (descending) with
// count(bins > T) < K <= count(bins >= T). nbins = 2048 -> per = 4.
// ---------------------------------------------------------------------------
__device__ void find_thresh512(const unsigned int* hist, int nbins, int K, int tid,
                               int* wsum, int* s_bin, int* s_above) {
    int per  = nbins >> 9;                 // 4
    int base = nbins - 1 - tid * per;
    int tsum = 0;
#pragma unroll
    for (int q = 0; q < 4; q++) tsum += (int)hist[base - q];

    int lane = tid & 31, wid = tid >> 5;   // 16 warps
    int x = tsum;
#pragma unroll
    for (int d = 1; d < 32; d <<= 1) {
        int n = __shfl_up_sync(0xffffffffu, x, d);
        if (lane >= d) x += n;
    }
    if (lane == 31) wsum[wid] = x;
    __syncthreads();
    if (wid == 0) {
        int w = (lane < 16) ? wsum[lane] : 0;
#pragma unroll
        for (int d = 1; d < 16; d <<= 1) {
            int n = __shfl_up_sync(0xffffffffu, w, d);
            if (lane >= d) w += n;
        }
        if (lane < 16) wsum[lane] = w;
    }
    __syncthreads();
    int excl = (wid == 0 ? 0 : wsum[wid - 1]) + (x - tsum);

    if (excl < K && excl + tsum >= K) {    // exactly one thread
        int c = excl;
        for (int q = 0; q < per; q++) {
            int bin = base - q;
            int h = (int)hist[bin];
            if (c + h >= K) { *s_bin = bin; *s_above = c; break; }
            c += h;
        }
    }
    __syncthreads();
}

// ---------------------------------------------------------------------------
// Fused persistent kernel: score -> (bar) -> topk (CTAs 0..31) -> (bar) -> decode
// ---------------------------------------------------------------------------
__global__ __launch_bounds__(NT, 2) void fused_kernel(
    const float* __restrict__ cls0, const float* __restrict__ cls1, const float* __restrict__ cls2,
    const float* __restrict__ bbox0, const float* __restrict__ bbox1, const float* __restrict__ bbox2,
    const float* __restrict__ obj0, const float* __restrict__ obj1, const float* __restrict__ obj2,
    const float* __restrict__ kpt0, const float* __restrict__ kpt1, const float* __restrict__ kpt2,
    const float* __restrict__ vis0, const float* __restrict__ vis1, const float* __restrict__ vis2,
    float* __restrict__ dout)
{
    __shared__ unsigned int       hist[NBINS];   // 8 KB: coarse / refine hist
    __shared__ unsigned int       hc[NBINS];     // 8 KB: candidates per bin
    __shared__ unsigned int       work[NBINS];   // 8 KB: cbase -> placement cursor
    __shared__ unsigned long long cand[NCAND];   // 16 KB: bin-grouped candidates
    __shared__ int  wsum[16];
    __shared__ int  s_bin, s_above;
    __shared__ unsigned int s_total;

    int tid  = threadIdx.x;
    int gtid = blockIdx.x * NT + tid;

    // ---------------- Phase A: scores (all CTAs, grid-strided float4) -------
    for (int i4 = gtid; i4 < NB * NA4; i4 += NTHR) {
        int b  = i4 / NA4;
        int a4 = i4 - b * NA4;
        const float4 *cp, *op;
        int p4;
        if (a4 < 6400)      { cp = (const float4*)cls0 + b * 6400; op = (const float4*)obj0 + b * 6400; p4 = a4; }
        else if (a4 < 8000) { cp = (const float4*)cls1 + b * 1600; op = (const float4*)obj1 + b * 1600; p4 = a4 - 6400; }
        else                { cp = (const float4*)cls2 + b * 400;  op = (const float4*)obj2 + b * 400;  p4 = a4 - 8000; }
        float4 c = cp[p4];
        float4 o = op[p4];
        float4 r;
        r.x = sigref(c.x) * sigref(o.x);
        r.y = sigref(c.y) * sigref(o.y);
        r.z = sigref(c.z) * sigref(o.z);
        r.w = sigref(c.w) * sigref(o.w);
        ((float4*)g_scores)[i4] = r;
    }

    grid_bar(0);

    // ---------------- Phase B: topk (CTAs 0..NB-1 only) ---------------------
    if (blockIdx.x < NB) {
        int b = blockIdx.x;
        const uint4* sv = (const uint4*)(g_scores + b * NA);

        // B1: coarse histogram on bits >> 19
        for (int q = tid; q < NBINS; q += NT) { hist[q] = 0u; hc[q] = 0u; }
        __syncthreads();
        for (int q = tid; q < NA4; q += NT) {
            uint4 v = sv[q];
            atomicAdd(&hist[v.x >> 19], 1u);
            atomicAdd(&hist[v.y >> 19], 1u);
            atomicAdd(&hist[v.z >> 19], 1u);
            atomicAdd(&hist[v.w >> 19], 1u);
        }
        __syncthreads();
        find_thresh512(hist, NBINS, K_TOP, tid, wsum, &s_bin, &s_above);
        int T = s_bin;
        int need2 = K_TOP - s_above;
        int binT_count = (int)hist[T];
        __syncthreads();

        unsigned int cut;
        if (s_above + binT_count <= NCAND) {
            cut = (unsigned int)T << 19;       // common case: fits buffer
        } else {
            // Rare: refine bin T on bits[18:8].
            for (int q = tid; q < NSUB; q += NT) hist[q] = 0u;
            __syncthreads();
            for (int q = tid; q < NA4; q += NT) {
                uint4 v = sv[q];
                if ((int)(v.x >> 19) == T) atomicAdd(&hist[(v.x >> 8) & 2047u], 1u);
                if ((int)(v.y >> 19) == T) atomicAdd(&hist[(v.y >> 8) & 2047u], 1u);
                if ((int)(v.z >> 19) == T) atomicAdd(&hist[(v.z >> 8) & 2047u], 1u);
                if ((int)(v.w >> 19) == T) atomicAdd(&hist[(v.w >> 8) & 2047u], 1u);
            }
            __syncthreads();
            find_thresh512(hist, NSUB, need2, tid, wsum, &s_bin, &s_above);
            cut = ((unsigned int)T << 19) | ((unsigned int)s_bin << 8);
            __syncthreads();
        }

        // B2: count candidates (bits >= cut) per coarse bin
        for (int q = tid; q < NA4; q += NT) {
            uint4 v = sv[q];
            if (v.x >= cut) atomicAdd(&hc[v.x >> 19], 1u);
            if (v.y >= cut) atomicAdd(&hc[v.y >> 19], 1u);
            if (v.z >= cut) atomicAdd(&hc[v.z >> 19], 1u);
            if (v.w >= cut) atomicAdd(&hc[v.w >> 19], 1u);
        }
        __syncthreads();

        // B3: descending suffix scan of hc -> work[bin] = #cands in bins > bin.
        {
            int hi = NBINS - 1 - 4 * tid;      // bins hi..hi-3
            unsigned int h3 = hc[hi], h2 = hc[hi - 1], h1 = hc[hi - 2], h0 = hc[hi - 3];
            int tsum = (int)(h3 + h2 + h1 + h0);
            int lane = tid & 31, wid = tid >> 5;
            int x = tsum;
#pragma unroll
            for (int d = 1; d < 32; d <<= 1) {
                int n = __shfl_up_sync(0xffffffffu, x, d);
                if (lane >= d) x += n;
            }
            if (lane == 31) wsum[wid] = x;
            __syncthreads();
            if (wid == 0) {
                int w = (lane < 16) ? wsum[lane] : 0;
#pragma unroll
                for (int d = 1; d < 16; d <<= 1) {
                    int n = __shfl_up_sync(0xffffffffu, w, d);
                    if (lane >= d) w += n;
                }
                if (lane < 16) wsum[lane] = w;
            }
            __syncthreads();
            int excl = (wid == 0 ? 0 : wsum[wid - 1]) + (x - tsum);
            work[hi]     = (unsigned int)excl;
            work[hi - 1] = (unsigned int)excl + h3;
            work[hi - 2] = (unsigned int)excl + h3 + h2;
            work[hi - 3] = (unsigned int)excl + h3 + h2 + h1;
            if (hi - 3 == 0) s_total = (unsigned int)(excl + tsum);
        }
        __syncthreads();

        // B4: place candidates grouped by bin; work[] is the cursor.
        // key = (bits << 32) | ~index : bigger key == better.
        for (int q = tid; q < NA4; q += NT) {
            uint4 v = sv[q];
            int a0 = q * 4;
#pragma unroll
            for (int e = 0; e < 4; e++) {
                unsigned int bits = (e == 0) ? v.x : (e == 1) ? v.y : (e == 2) ? v.z : v.w;
                if (bits >= cut) {
                    unsigned int bin = bits >> 19;
                    unsigned int slot = atomicAdd(&work[bin], 1u);
                    if (slot < NCAND)
                        cand[slot] = ((unsigned long long)bits << 32) |
                                     (unsigned long long)(0xFFFFFFFFu - (unsigned int)(a0 + e));
                }
            }
        }
        __syncthreads();
        int cnt = (int)s_total; if (cnt > NCAND) cnt = NCAND;
        // After B4: work[bin] = cbase[bin] + hc[bin] (group end, uncapped).

        // B5: exact rank = start + #same-bin candidates with larger key.
        for (int s = tid; s < cnt; s += NT) {
            unsigned long long key = cand[s];
            unsigned int bin   = (unsigned int)(key >> 51);   // bits<2^30 -> bin<2048
            unsigned int endr  = work[bin];
            unsigned int start = endr - hc[bin];
            unsigned int end   = endr; if (end > (unsigned int)cnt) end = (unsigned int)cnt;
            int r = (int)start;
            for (unsigned int g = start; g < end; g++)
                r += (cand[g] > key);
            if (r < K_TOP) {
                unsigned int bits = (unsigned int)(key >> 32);
                unsigned int a    = 0xFFFFFFFFu - (unsigned int)(key & 0xFFFFFFFFull);
                g_keep[b * K_TOP + r] = (int)a;
                dout[b * (K_TOP * 5) + r * 5 + 4] = __uint_as_float(bits);
            }
        }
    }

    grid_bar(1);

    // ---------------- Phase C: decode (all CTAs, 9 subs/det) ----------------
    // sub 0..7 -> keypoint pair (2s, 2s+1): 6 loads; sub 8 -> kpt16 + bbox: 7.
    for (int t = gtid; t < NDET * 9; t += NTHR) {
        int det = t % NDET;
        int s9  = t / NDET;
        int b   = det / K_TOP;
        int a   = g_keep[det];

        int p, HW, l;
        float sc, px, py;
        if (a < 25600)      { p = a;         HW = 25600; sc = 8.0f;  l = 0; px = (float)(p % 160) * 8.0f;  py = (float)(p / 160) * 8.0f;  }
        else if (a < 32000) { p = a - 25600; HW = 6400;  sc = 16.0f; l = 1; px = (float)(p % 80)  * 16.0f; py = (float)(p / 80)  * 16.0f; }
        else                { p = a - 32000; HW = 1600;  sc = 32.0f; l = 2; px = (float)(p % 40)  * 32.0f; py = (float)(p / 40)  * 32.0f; }

        const float* kp = (l == 0) ? kpt0 : (l == 1) ? kpt1 : kpt2;
        const float* vp = (l == 0) ? vis0 : (l == 1) ? vis1 : vis2;
        int koff = NDET * 5 + det * 51;

        if (s9 < 8) {
            int k0 = 2 * s9, k1 = 2 * s9 + 1;
            float kx0 = kp[(b * 34 + 2 * k0)     * HW + p];
            float ky0 = kp[(b * 34 + 2 * k0 + 1) * HW + p];
            float kx1 = kp[(b * 34 + 2 * k1)     * HW + p];
            float ky1 = kp[(b * 34 + 2 * k1 + 1) * HW + p];
            float v0  = vp[(b * 17 + k0)         * HW + p];
            float v1  = vp[(b * 17 + k1)         * HW + p];
            dout[koff + k0 * 3 + 0] = kx0 * sc + px;
            dout[koff + k0 * 3 + 1] = ky0 * sc + py;
            dout[koff + k0 * 3 + 2] = sigref(v0);
            dout[koff + k1 * 3 + 0] = kx1 * sc + px;
            dout[koff + k1 * 3 + 1] = ky1 * sc + py;
            dout[koff + k1 * 3 + 2] = sigref(v1);
        } else {
            // kpt 16
            float kx = kp[(b * 34 + 32) * HW + p];
            float ky = kp[(b * 34 + 33) * HW + p];
            float v  = vp[(b * 17 + 16) * HW + p];
            dout[koff + 48] = kx * sc + px;
            dout[koff + 49] = ky * sc + py;
            dout[koff + 50] = sigref(v);
            // bbox
            const float* bp = (l == 0) ? bbox0 : (l == 1) ? bbox1 : bbox2;
            float bx = bp[(b * 4 + 0) * HW + p];
            float by = bp[(b * 4 + 1) * HW + p];
            float bw = bp[(b * 4 + 2) * HW + p];
            float bh = bp[(b * 4 + 3) * HW + p];
            float x  = bx * sc + px;
            float y  = by * sc + py;
            float hw = expf(bw) * sc * 0.5f;
            float hh = expf(bh) * sc * 0.5f;
            int off = det * 5;
            dout[off + 0] = x - hw;
            dout[off + 1] = y - hh;
            dout[off + 2] = x + hw;
            dout[off + 3] = y + hh;
        }
    }
}

// ---------------------------------------------------------------------------
extern "C" void kernel_launch(void* const* d_in, const int* in_sizes, int n_in,
                              void* d_out, int out_size) {
    const float* cls0  = (const float*)d_in[0];
    const float* cls1  = (const float*)d_in[1];
    const float* cls2  = (const float*)d_in[2];
    const float* bbox0 = (const float*)d_in[3];
    const float* bbox1 = (const float*)d_in[4];
    const float* bbox2 = (const float*)d_in[5];
    const float* obj0  = (const float*)d_in[6];
    const float* obj1  = (const float*)d_in[7];
    const float* obj2  = (const float*)d_in[8];
    const float* kpt0  = (const float*)d_in[9];
    const float* kpt1  = (const float*)d_in[10];
    const float* kpt2  = (const float*)d_in[11];
    const float* vis0  = (const float*)d_in[12];
    const float* vis1  = (const float*)d_in[13];
    const float* vis2  = (const float*)d_in[14];
    float* dout = (float*)d_out;

    zero_bar<<<1, 32>>>();
    fused_kernel<<<NBLK, NT>>>(cls0, cls1, cls2, bbox0, bbox1, bbox2,
                               obj0, obj1, obj2, kpt0, kpt1, kpt2,
                               vis0, vis1, vis2, dout);
}

// round 11
// speedup vs baseline: 1.1747x; 1.1747x over previous
#include <cuda_runtime.h>
#include <math.h>

#define NB     32
#define NA     33600
#define K_TOP  1000
#define NBINS  2048      // coarse bins: score_bits >> 19
#define NSUB   2048      // refine bins: bits[18:8]
#define NCAND  2048
#define NA4    (NA / 4)  // 8400
#define NIT    9         // ceil(NA4 / 1024) register-cache iterations
#define NDET   (NB * K_TOP)

// scratch (static device globals — no allocation)
__device__ float g_scores[NB * NA];   // 4.3 MB, L2-resident
__device__ int   g_keep[NDET];        // anchor per (batch, rank)

// Bitwise match of XLA GPU logistic: 1/(1+exp(-x)) with libdevice expf and
// IEEE div.rn (nvcc defaults, no fast-math). DO NOT refactor algebraically —
// output ordering must be bit-exact vs reference (rel_err 5e-9 confirms).
__device__ __forceinline__ float sigref(float x) {
    return 1.0f / (1.0f + expf(-x));
}

// ---------------------------------------------------------------------------
// Kernel 1: score[b,a] = sigmoid(cls)*sigmoid(obj), float4-vectorized.
// (measured ~6.2-6.5us — unchanged from R9)
// ---------------------------------------------------------------------------
__global__ void score_kernel(const float* __restrict__ cls0, const float* __restrict__ cls1,
                             const float* __restrict__ cls2,
                             const float* __restrict__ obj0, const float* __restrict__ obj1,
                             const float* __restrict__ obj2) {
    int i4 = blockIdx.x * blockDim.x + threadIdx.x;
    if (i4 >= NB * NA4) return;
    int b  = i4 / NA4;
    int a4 = i4 - b * NA4;
    const float4 *cp, *op;
    int p4;
    if (a4 < 6400)      { cp = (const float4*)cls0 + b * 6400; op = (const float4*)obj0 + b * 6400; p4 = a4; }
    else if (a4 < 8000) { cp = (const float4*)cls1 + b * 1600; op = (const float4*)obj1 + b * 1600; p4 = a4 - 6400; }
    else                { cp = (const float4*)cls2 + b * 400;  op = (const float4*)obj2 + b * 400;  p4 = a4 - 8000; }
    float4 c = cp[p4];
    float4 o = op[p4];
    float4 r;
    r.x = sigref(c.x) * sigref(o.x);
    r.y = sigref(c.y) * sigref(o.y);
    r.z = sigref(c.z) * sigref(o.z);
    r.w = sigref(c.w) * sigref(o.w);
    ((float4*)g_scores)[i4] = r;
}

// ---------------------------------------------------------------------------
// Kernel 2: exact sorted top-1000 per batch (one CTA per batch, 1024 threads)
// Histogram-rank (R9, measured WIN): no comparison sort, ~7 barriers total.
// ---------------------------------------------------------------------------
__device__ void find_thresh(const unsigned int* hist, int nbins, int K, int tid,
                            int* wsum, int* s_bin, int* s_above) {
    int per  = nbins >> 10;
    int base = nbins - 1 - tid * per;
    int tsum = 0;
    for (int q = 0; q < per; q++) tsum += (int)hist[base - q];

    int lane = tid & 31, wid = tid >> 5;
    int x = tsum;
#pragma unroll
    for (int d = 1; d < 32; d <<= 1) {
        int n = __shfl_up_sync(0xffffffffu, x, d);
        if (lane >= d) x += n;
    }
    if (lane == 31) wsum[wid] = x;
    __syncthreads();
    if (wid == 0) {
        int w = wsum[lane];
#pragma unroll
        for (int d = 1; d < 32; d <<= 1) {
            int n = __shfl_up_sync(0xffffffffu, w, d);
            if (lane >= d) w += n;
        }
        wsum[lane] = w;
    }
    __syncthreads();
    int excl = (wid == 0 ? 0 : wsum[wid - 1]) + (x - tsum);

    if (excl < K && excl + tsum >= K) {     // exactly one thread
        int c = excl;
        for (int q = 0; q < per; q++) {
            int bin = base - q;
            int h = (int)hist[bin];
            if (c + h >= K) { *s_bin = bin; *s_above = c; break; }
            c += h;
        }
    }
    __syncthreads();
}

__global__ __launch_bounds__(1024) void topk_kernel(float* __restrict__ dout) {
    __shared__ unsigned int       hist[NBINS];    // 8 KB: coarse hist / refine hist
    __shared__ unsigned int       hc[NBINS];      // 8 KB: candidate count per bin
    __shared__ unsigned int       cbase[NBINS];   // 8 KB: suffix-scan group base
    __shared__ unsigned int       cur[NBINS];     // 8 KB: placement cursor per bin
    __shared__ unsigned long long cand[NCAND];    // 16 KB: bin-grouped candidates
    __shared__ int  wsum[32];
    __shared__ int  s_bin, s_above;
    __shared__ unsigned int s_total;

    int b = blockIdx.x;
    int tid = threadIdx.x;
    const uint4* sv = (const uint4*)(g_scores + b * NA);

    // Register-cache this thread's 9 uint4 chunks (single L2 read pass).
    uint4 vloc[NIT];
#pragma unroll
    for (int it = 0; it < NIT; it++) {
        int q = it * 1024 + tid;
        vloc[it] = (q < NA4) ? sv[q] : make_uint4(0u, 0u, 0u, 0u);
    }

    // Phase 1: coarse histogram on bits >> 19.
    for (int q = tid; q < NBINS; q += 1024) { hist[q] = 0u; hc[q] = 0u; cur[q] = 0u; }
    __syncthreads();
#pragma unroll
    for (int it = 0; it < NIT; it++) {
        uint4 v = vloc[it];
        atomicAdd(&hist[v.x >> 19], 1u);
        atomicAdd(&hist[v.y >> 19], 1u);
        atomicAdd(&hist[v.z >> 19], 1u);
        atomicAdd(&hist[v.w >> 19], 1u);
    }
    __syncthreads();
    find_thresh(hist, NBINS, K_TOP, tid, wsum, &s_bin, &s_above);
    int T = s_bin;
    int need2 = K_TOP - s_above;
    int binT_count = (int)hist[T];
    __syncthreads();

    unsigned int cut;
    if (s_above + binT_count <= NCAND) {
        cut = (unsigned int)T << 19;            // common case: candidates fit buffer
    } else {
        // Rare: refine bin T on bits[18:8] to bound candidate count.
        for (int q = tid; q < NSUB; q += 1024) hist[q] = 0u;
        __syncthreads();
#pragma unroll
        for (int it = 0; it < NIT; it++) {
            uint4 v = vloc[it];
            if ((int)(v.x >> 19) == T) atomicAdd(&hist[(v.x >> 8) & 2047u], 1u);
            if ((int)(v.y >> 19) == T) atomicAdd(&hist[(v.y >> 8) & 2047u], 1u);
            if ((int)(v.z >> 19) == T) atomicAdd(&hist[(v.z >> 8) & 2047u], 1u);
            if ((int)(v.w >> 19) == T) atomicAdd(&hist[(v.w >> 8) & 2047u], 1u);
        }
        __syncthreads();
        find_thresh(hist, NSUB, need2, tid, wsum, &s_bin, &s_above);
        cut = ((unsigned int)T << 19) | ((unsigned int)s_bin << 8);
        __syncthreads();
    }

    // Phase 2: count candidates (bits >= cut) per coarse bin.
#pragma unroll
    for (int it = 0; it < NIT; it++) {
        uint4 v = vloc[it];
        if (v.x >= cut) atomicAdd(&hc[v.x >> 19], 1u);
        if (v.y >= cut) atomicAdd(&hc[v.y >> 19], 1u);
        if (v.z >= cut) atomicAdd(&hc[v.z >> 19], 1u);
        if (v.w >= cut) atomicAdd(&hc[v.w >> 19], 1u);
    }
    __syncthreads();

    // Phase 3: descending suffix scan of hc -> cbase[bin] = #cands in bins > bin.
    {
        int hi = NBINS - 1 - 2 * tid;
        unsigned int h1 = hc[hi], h0 = hc[hi - 1];
        int tsum = (int)(h1 + h0);
        int lane = tid & 31, wid = tid >> 5;
        int x = tsum;
#pragma unroll
        for (int d = 1; d < 32; d <<= 1) {
            int n = __shfl_up_sync(0xffffffffu, x, d);
            if (lane >= d) x += n;
        }
        if (lane == 31) wsum[wid] = x;
        __syncthreads();
        if (wid == 0) {
            int w = wsum[lane];
#pragma unroll
            for (int d = 1; d < 32; d <<= 1) {
                int n = __shfl_up_sync(0xffffffffu, w, d);
                if (lane >= d) w += n;
            }
            wsum[lane] = w;
        }
        __syncthreads();
        int excl = (wid == 0 ? 0 : wsum[wid - 1]) + (x - tsum);
        cbase[hi]     = (unsigned int)excl;
        cbase[hi - 1] = (unsigned int)excl + h1;
        if (hi - 1 == 0)
            s_total = (unsigned int)excl + h1 + h0;
    }
    __syncthreads();

    // Phase 4: place candidates grouped by bin: slot = cbase[bin] + cur[bin]++.
#pragma unroll
    for (int it = 0; it < NIT; it++) {
        uint4 v = vloc[it];
        int a0 = (it * 1024 + tid) * 4;
#pragma unroll
        for (int e = 0; e < 4; e++) {
            unsigned int bits = (e == 0) ? v.x : (e == 1) ? v.y : (e == 2) ? v.z : v.w;
            if (bits >= cut) {
                unsigned int bin = bits >> 19;
                unsigned int slot = cbase[bin] + atomicAdd(&cur[bin], 1u);
                if (slot < NCAND)
                    cand[slot] = ((unsigned long long)bits << 32) |
                                 (unsigned long long)(0xFFFFFFFFu - (unsigned int)(a0 + e));
            }
        }
    }
    __syncthreads();
    int cnt = (int)s_total; if (cnt > NCAND) cnt = NCAND;

    // Phase 5: exact rank = cbase[bin] + #same-bin candidates with larger key.
#pragma unroll
    for (int s0 = 0; s0 < 2; s0++) {
        int s = tid + s0 * 1024;
        if (s < cnt) {
            unsigned long long key = cand[s];
            unsigned int bin   = (unsigned int)(key >> 51);
            unsigned int start = cbase[bin];
            unsigned int end   = start + hc[bin];
            if (end > (unsigned int)cnt) end = (unsigned int)cnt;
            int r = (int)start;
            for (unsigned int g = start; g < end; g++)
                r += (cand[g] > key);
            if (r < K_TOP) {
                unsigned int bits = (unsigned int)(key >> 32);
                unsigned int a    = 0xFFFFFFFFu - (unsigned int)(key & 0xFFFFFFFFull);
                g_keep[b * K_TOP + r] = (int)a;
                dout[b * (K_TOP * 5) + r * 5 + 4] = __uint_as_float(bits);
            }
        }
    }
}

// ---------------------------------------------------------------------------
// Kernel 3: decode. 9 subs per detection (8 keypoint-pairs + kpt16&bbox):
// 6-7 outstanding gathers per thread (2-3x the R9 MLP) to push DRAM toward
// its streaming rate. det is the fast index.
// ---------------------------------------------------------------------------
__global__ void decode_kernel(const float* __restrict__ bbox0, const float* __restrict__ bbox1,
                              const float* __restrict__ bbox2,
                              const float* __restrict__ kpt0,  const float* __restrict__ kpt1,
                              const float* __restrict__ kpt2,
                              const float* __restrict__ vis0,  const float* __restrict__ vis1,
                              const float* __restrict__ vis2,
                              float* __restrict__ dout) {
    const int NTASK = NDET * 9;
    int t = blockIdx.x * blockDim.x + threadIdx.x;
    if (t >= NTASK) return;
    int det = t % NDET;
    int s9  = t / NDET;
    int b   = det / K_TOP;
    int a   = g_keep[det];

    int p, HW, l;
    float sc, px, py;
    if (a < 25600)      { p = a;         HW = 25600; sc = 8.0f;  l = 0; px = (float)(p % 160) * 8.0f;  py = (float)(p / 160) * 8.0f;  }
    else if (a < 32000) { p = a - 25600; HW = 6400;  sc = 16.0f; l = 1; px = (float)(p % 80)  * 16.0f; py = (float)(p / 80)  * 16.0f; }
    else                { p = a - 32000; HW = 1600;  sc = 32.0f; l = 2; px = (float)(p % 40)  * 32.0f; py = (float)(p / 40)  * 32.0f; }

    const float* kp = (l == 0) ? kpt0 : (l == 1) ? kpt1 : kpt2;
    const float* vp = (l == 0) ? vis0 : (l == 1) ? vis1 : vis2;
    int koff = NDET * 5 + det * 51;

    if (s9 < 8) {
        int k0 = 2 * s9, k1 = 2 * s9 + 1;
        float kx0 = kp[(b * 34 + 2 * k0)     * HW + p];
        float ky0 = kp[(b * 34 + 2 * k0 + 1) * HW + p];
        float kx1 = kp[(b * 34 + 2 * k1)     * HW + p];
        float ky1 = kp[(b * 34 + 2 * k1 + 1) * HW + p];
        float v0  = vp[(b * 17 + k0)         * HW + p];
        float v1  = vp[(b * 17 + k1)         * HW + p];
        dout[koff + k0 * 3 + 0] = kx0 * sc + px;
        dout[koff + k0 * 3 + 1] = ky0 * sc + py;
        dout[koff + k0 * 3 + 2] = sigref(v0);
        dout[koff + k1 * 3 + 0] = kx1 * sc + px;
        dout[koff + k1 * 3 + 1] = ky1 * sc + py;
        dout[koff + k1 * 3 + 2] = sigref(v1);
    } else {
        // kpt 16
        float kx = kp[(b * 34 + 32) * HW + p];
        float ky = kp[(b * 34 + 33) * HW + p];
        float v  = vp[(b * 17 + 16) * HW + p];
        dout[koff + 48] = kx * sc + px;
        dout[koff + 49] = ky * sc + py;
        dout[koff + 50] = sigref(v);
        // bbox
        const float* bp = (l == 0) ? bbox0 : (l == 1) ? bbox1 : bbox2;
        float bx = bp[(b * 4 + 0) * HW + p];
        float by = bp[(b * 4 + 1) * HW + p];
        float bw = bp[(b * 4 + 2) * HW + p];
        float bh = bp[(b * 4 + 3) * HW + p];
        float x  = bx * sc + px;
        float y  = by * sc + py;
        float hw = expf(bw) * sc * 0.5f;
        float hh = expf(bh) * sc * 0.5f;
        int off = det * 5;
        dout[off + 0] = x - hw;
        dout[off + 1] = y - hh;
        dout[off + 2] = x + hw;
        dout[off + 3] = y + hh;
    }
}

// ---------------------------------------------------------------------------
extern "C" void kernel_launch(void* const* d_in, const int* in_sizes, int n_in,
                              void* d_out, int out_size) {
    const float* cls0  = (const float*)d_in[0];
    const float* cls1  = (const float*)d_in[1];
    const float* cls2  = (const float*)d_in[2];
    const float* bbox0 = (const float*)d_in[3];
    const float* bbox1 = (const float*)d_in[4];
    const float* bbox2 = (const float*)d_in[5];
    const float* obj0  = (const float*)d_in[6];
    const float* obj1  = (const float*)d_in[7];
    const float* obj2  = (const float*)d_in[8];
    const float* kpt0  = (const float*)d_in[9];
    const float* kpt1  = (const float*)d_in[10];
    const float* kpt2  = (const float*)d_in[11];
    const float* vis0  = (const float*)d_in[12];
    const float* vis1  = (const float*)d_in[13];
    const float* vis2  = (const float*)d_in[14];
    float* dout = (float*)d_out;

    score_kernel<<<(NB * NA4 + 255) / 256, 256>>>(cls0, cls1, cls2, obj0, obj1, obj2);
    topk_kernel<<<NB, 1024>>>(dout);
    decode_kernel<<<(NDET * 9 + 255) / 256, 256>>>(bbox0, bbox1, bbox2,
                                                   kpt0, kpt1, kpt2,
                                                   vis0, vis1, vis2, dout);
}

// round 13
// speedup vs baseline: 1.2497x; 1.0639x over previous
#include <cuda_runtime.h>
#include <math.h>

#define NB     32
#define NA     33600
#define K_TOP  1000
#define NBINS  2048      // coarse bins: score_bits >> 19
#define NSUB   2048      // refine bins: bits[18:8]
#define NCAND  2048
#define NA4    (NA / 4)  // 8400
#define NDET   (NB * K_TOP)

// scratch (static device globals — no allocation)
__device__ float g_scores[NB * NA];   // 4.3 MB, L2-resident
__device__ int   g_keep[NDET];        // anchor per (batch, rank)

// Bitwise match of XLA GPU logistic: 1/(1+exp(-x)) with libdevice expf and
// IEEE div.rn (nvcc defaults, no fast-math). DO NOT refactor algebraically —
// output ordering must be bit-exact vs reference (rel_err 5e-9 confirms).
__device__ __forceinline__ float sigref(float x) {
    return 1.0f / (1.0f + expf(-x));
}

// ---------------------------------------------------------------------------
// Kernel 1: score[b,a] = sigmoid(cls)*sigmoid(obj), float4-vectorized.
// (measured ~6.2-6.5us — unchanged)
// ---------------------------------------------------------------------------
__global__ void score_kernel(const float* __restrict__ cls0, const float* __restrict__ cls1,
                             const float* __restrict__ cls2,
                             const float* __restrict__ obj0, const float* __restrict__ obj1,
                             const float* __restrict__ obj2) {
    int i4 = blockIdx.x * blockDim.x + threadIdx.x;
    if (i4 >= NB * NA4) return;
    int b  = i4 / NA4;
    int a4 = i4 - b * NA4;
    const float4 *cp, *op;
    int p4;
    if (a4 < 6400)      { cp = (const float4*)cls0 + b * 6400; op = (const float4*)obj0 + b * 6400; p4 = a4; }
    else if (a4 < 8000) { cp = (const float4*)cls1 + b * 1600; op = (const float4*)obj1 + b * 1600; p4 = a4 - 6400; }
    else                { cp = (const float4*)cls2 + b * 400;  op = (const float4*)obj2 + b * 400;  p4 = a4 - 8000; }
    float4 c = cp[p4];
    float4 o = op[p4];
    float4 r;
    r.x = sigref(c.x) * sigref(o.x);
    r.y = sigref(c.y) * sigref(o.y);
    r.z = sigref(c.z) * sigref(o.z);
    r.w = sigref(c.w) * sigref(o.w);
    ((float4*)g_scores)[i4] = r;
}

// ---------------------------------------------------------------------------
// Kernel 2: exact sorted top-1000 per batch (one CTA per batch, 1024 threads)
// Histogram-rank, 2 data passes (was 3), no register cache (spill relief).
// ---------------------------------------------------------------------------
__device__ void find_thresh(const unsigned int* hist, int nbins, int K, int tid,
                            int* wsum, int* s_bin, int* s_above) {
    int per  = nbins >> 10;
    int base = nbins - 1 - tid * per;
    int tsum = 0;
    for (int q = 0; q < per; q++) tsum += (int)hist[base - q];

    int lane = tid & 31, wid = tid >> 5;
    int x = tsum;
#pragma unroll
    for (int d = 1; d < 32; d <<= 1) {
        int n = __shfl_up_sync(0xffffffffu, x, d);
        if (lane >= d) x += n;
    }
    if (lane == 31) wsum[wid] = x;
    __syncthreads();
    if (wid == 0) {
        int w = wsum[lane];
#pragma unroll
        for (int d = 1; d < 32; d <<= 1) {
            int n = __shfl_up_sync(0xffffffffu, w, d);
            if (lane >= d) w += n;
        }
        wsum[lane] = w;
    }
    __syncthreads();
    int excl = (wid == 0 ? 0 : wsum[wid - 1]) + (x - tsum);

    if (excl < K && excl + tsum >= K) {     // exactly one thread
        int c = excl;
        for (int q = 0; q < per; q++) {
            int bin = base - q;
            int h = (int)hist[bin];
            if (c + h >= K) { *s_bin = bin; *s_above = c; break; }
            c += h;
        }
    }
    __syncthreads();
}

__global__ __launch_bounds__(1024) void topk_kernel(float* __restrict__ dout) {
    __shared__ unsigned int       hist[NBINS];    // 8 KB: coarse hist (preserved)
    __shared__ unsigned int       scanv[NBINS];   // 8 KB: refine hist -> cbase -> group end
    __shared__ unsigned long long cand[NCAND];    // 16 KB: bin-grouped candidates
    __shared__ int  wsum[32];
    __shared__ int  s_bin, s_above;
    __shared__ unsigned int s_total;

    int b = blockIdx.x;
    int tid = threadIdx.x;
    const uint4* sv = (const uint4*)(g_scores + b * NA);

    // Phase 1: coarse histogram on bits >> 19 (pass 1 over L2-resident scores).
    for (int q = tid; q < NBINS; q += 1024) hist[q] = 0u;
    __syncthreads();
    for (int q = tid; q < NA4; q += 1024) {
        uint4 v = sv[q];
        atomicAdd(&hist[v.x >> 19], 1u);
        atomicAdd(&hist[v.y >> 19], 1u);
        atomicAdd(&hist[v.z >> 19], 1u);
        atomicAdd(&hist[v.w >> 19], 1u);
    }
    __syncthreads();
    find_thresh(hist, NBINS, K_TOP, tid, wsum, &s_bin, &s_above);
    int T = s_bin;
    int need2 = K_TOP - s_above;
    int binT_count = (int)hist[T];
    __syncthreads();

    // Candidate count per bin is ALREADY hist[] for bins > T; only bin T's
    // kept-count differs when we refine. No extra counting pass needed.
    unsigned int cut;
    int keptT;
    if (s_above + binT_count <= NCAND) {
        cut = (unsigned int)T << 19;        // keep all of bin T
        keptT = binT_count;
    } else {
        // Rare: refine bin T on bits[18:8] (uses scanv as the sub-histogram).
        for (int q = tid; q < NSUB; q += 1024) scanv[q] = 0u;
        __syncthreads();
        for (int q = tid; q < NA4; q += 1024) {
            uint4 v = sv[q];
            if ((int)(v.x >> 19) == T) atomicAdd(&scanv[(v.x >> 8) & 2047u], 1u);
            if ((int)(v.y >> 19) == T) atomicAdd(&scanv[(v.y >> 8) & 2047u], 1u);
            if ((int)(v.z >> 19) == T) atomicAdd(&scanv[(v.z >> 8) & 2047u], 1u);
            if ((int)(v.w >> 19) == T) atomicAdd(&scanv[(v.w >> 8) & 2047u], 1u);
        }
        __syncthreads();
        find_thresh(scanv, NSUB, need2, tid, wsum, &s_bin, &s_above);
        cut = ((unsigned int)T << 19) | ((unsigned int)s_bin << 8);
        keptT = s_above + (int)scanv[s_bin];   // kept members of bin T
        __syncthreads();
    }

    // Phase 2: descending suffix scan of masked hist -> scanv[bin] = cbase.
    // val(bin) = hist[bin] for bin > T, keptT at T, 0 below.
    {
        int hi = NBINS - 1 - 2 * tid;
        unsigned int h1 = (hi > T) ? hist[hi] : (hi == T ? (unsigned int)keptT : 0u);
        int lo = hi - 1;
        unsigned int h0 = (lo > T) ? hist[lo] : (lo == T ? (unsigned int)keptT : 0u);
        int tsum = (int)(h1 + h0);
        int lane = tid & 31, wid = tid >> 5;
        int x = tsum;
#pragma unroll
        for (int d = 1; d < 32; d <<= 1) {
            int n = __shfl_up_sync(0xffffffffu, x, d);
            if (lane >= d) x += n;
        }
        if (lane == 31) wsum[wid] = x;
        __syncthreads();
        if (wid == 0) {
            int w = wsum[lane];
#pragma unroll
            for (int d = 1; d < 32; d <<= 1) {
                int n = __shfl_up_sync(0xffffffffu, w, d);
                if (lane >= d) w += n;
            }
            wsum[lane] = w;
        }
        __syncthreads();
        int excl = (wid == 0 ? 0 : wsum[wid - 1]) + (x - tsum);
        scanv[hi] = (unsigned int)excl;
        scanv[lo] = (unsigned int)excl + h1;
        if (lo == 0) s_total = (unsigned int)(excl + tsum);
    }
    __syncthreads();

    // Phase 3: place candidates grouped by bin (pass 2 over L2).
    // scanv[bin] is the cursor; after this phase scanv[bin] = group END.
    // key = (bits << 32) | ~index : bigger key == better (score desc, idx asc).
    for (int q = tid; q < NA4; q += 1024) {
        uint4 v = sv[q];
        int a0 = q * 4;
#pragma unroll
        for (int e = 0; e < 4; e++) {
            unsigned int bits = (e == 0) ? v.x : (e == 1) ? v.y : (e == 2) ? v.z : v.w;
            if (bits >= cut) {
                unsigned int bin = bits >> 19;
                unsigned int slot = atomicAdd(&scanv[bin], 1u);
                if (slot < NCAND)
                    cand[slot] = ((unsigned long long)bits << 32) |
                                 (unsigned long long)(0xFFFFFFFFu - (unsigned int)(a0 + e));
            }
        }
    }
    __syncthreads();
    int cnt = (int)s_total; if (cnt > NCAND) cnt = NCAND;

    // Phase 4: exact rank = group_start + #same-group candidates with larger key.
    // group end = scanv[bin]; size = hist[bin] (bin > T) or keptT (bin == T).
#pragma unroll
    for (int s0 = 0; s0 < 2; s0++) {
        int s = tid + s0 * 1024;
        if (s < cnt) {
            unsigned long long key = cand[s];
            unsigned int bin  = (unsigned int)(key >> 51);   // bits<2^30 -> bin<2048
            unsigned int endr = scanv[bin];
            unsigned int size = ((int)bin == T) ? (unsigned int)keptT : hist[bin];
            unsigned int start = endr - size;
            unsigned int end   = endr; if (end > (unsigned int)cnt) end = (unsigned int)cnt;
            int r = (int)start;
            for (unsigned int g = start; g < end; g++)
                r += (cand[g] > key);
            if (r < K_TOP) {
                unsigned int bits = (unsigned int)(key >> 32);
                unsigned int a    = 0xFFFFFFFFu - (unsigned int)(key & 0xFFFFFFFFull);
                g_keep[b * K_TOP + r] = (int)a;
                dout[b * (K_TOP * 5) + r * 5 + 4] = __uint_as_float(bits);
            }
        }
    }
}

// ---------------------------------------------------------------------------
// Kernel 3: decode kept anchors. 18 tasks/det, det fast index (R9 measured-best).
// ---------------------------------------------------------------------------
__global__ void decode_kernel(const float* __restrict__ bbox0, const float* __restrict__ bbox1,
                              const float* __restrict__ bbox2,
                              const float* __restrict__ kpt0,  const float* __restrict__ kpt1,
                              const float* __restrict__ kpt2,
                              const float* __restrict__ vis0,  const float* __restrict__ vis1,
                              const float* __restrict__ vis2,
                              float* __restrict__ dout) {
    const int NTASK = NDET * 18;
    int task = blockIdx.x * blockDim.x + threadIdx.x;
    if (task >= NTASK) return;
    int det = task % NDET;
    int sub = task / NDET;
    int b   = det / K_TOP;
    int a   = g_keep[det];

    int p, HW, l;
    float s, px, py;
    if (a < 25600)      { p = a;         HW = 25600; s = 8.0f;  l = 0; px = (float)(p % 160) * 8.0f;  py = (float)(p / 160) * 8.0f;  }
    else if (a < 32000) { p = a - 25600; HW = 6400;  s = 16.0f; l = 1; px = (float)(p % 80)  * 16.0f; py = (float)(p / 80)  * 16.0f; }
    else                { p = a - 32000; HW = 1600;  s = 32.0f; l = 2; px = (float)(p % 40)  * 32.0f; py = (float)(p / 40)  * 32.0f; }

    if (sub < 17) {
        int k = sub;
        const float* kp = (l == 0) ? kpt0 : (l == 1) ? kpt1 : kpt2;
        const float* vp = (l == 0) ? vis0 : (l == 1) ? vis1 : vis2;
        float kx = kp[(b * 34 + 2 * k)     * HW + p];
        float ky = kp[(b * 34 + 2 * k + 1) * HW + p];
        float v  = vp[(b * 17 + k)         * HW + p];
        int off = NDET * 5 + det * 51 + k * 3;
        dout[off + 0] = kx * s + px;
        dout[off + 1] = ky * s + py;
        dout[off + 2] = sigref(v);
    } else {
        const float* bp = (l == 0) ? bbox0 : (l == 1) ? bbox1 : bbox2;
        float bx = bp[(b * 4 + 0) * HW + p];
        float by = bp[(b * 4 + 1) * HW + p];
        float bw = bp[(b * 4 + 2) * HW + p];
        float bh = bp[(b * 4 + 3) * HW + p];
        float x  = bx * s + px;
        float y  = by * s + py;
        float hw = expf(bw) * s * 0.5f;
        float hh = expf(bh) * s * 0.5f;
        int off = det * 5;
        dout[off + 0] = x - hw;
        dout[off + 1] = y - hh;
        dout[off + 2] = x + hw;
        dout[off + 3] = y + hh;
    }
}

// ---------------------------------------------------------------------------
extern "C" void kernel_launch(void* const* d_in, const int* in_sizes, int n_in,
                              void* d_out, int out_size) {
    const float* cls0  = (const float*)d_in[0];
    const float* cls1  = (const float*)d_in[1];
    const float* cls2  = (const float*)d_in[2];
    const float* bbox0 = (const float*)d_in[3];
    const float* bbox1 = (const float*)d_in[4];
    const float* bbox2 = (const float*)d_in[5];
    const float* obj0  = (const float*)d_in[6];
    const float* obj1  = (const float*)d_in[7];
    const float* obj2  = (const float*)d_in[8];
    const float* kpt0  = (const float*)d_in[9];
    const float* kpt1  = (const float*)d_in[10];
    const float* kpt2  = (const float*)d_in[11];
    const float* vis0  = (const float*)d_in[12];
    const float* vis1  = (const float*)d_in[13];
    const float* vis2  = (const float*)d_in[14];
    float* dout = (float*)d_out;

    score_kernel<<<(NB * NA4 + 255) / 256, 256>>>(cls0, cls1, cls2, obj0, obj1, obj2);
    topk_kernel<<<NB, 1024>>>(dout);
    decode_kernel<<<(NDET * 18 + 255) / 256, 256>>>(bbox0, bbox1, bbox2,
                                                    kpt0, kpt1, kpt2,
                                                    vis0, vis1, vis2, dout);
}